// round 15
// baseline (speedup 1.0000x reference)
#include <cuda_runtime.h>
#include <cstdint>

// Problem constants
#define B_   2
#define S_   4096
#define H_   16
#define D_   128
#define HID_ 2048
#define C_   128
#define NC_  32
#define M_   (B_*S_)   // 8192 rows
#define EPS_ 1e-6f
#define QROW (3*HID_)  // 6144: fused q|k|v row stride

// ---------------- scratch (device globals; no allocs allowed) ----------------
__device__ float g_qkv[(size_t)M_*QROW];          // [M][q|k|v]
__device__ float g_attn[(size_t)M_*HID_];
__device__ float g_kv[(size_t)B_*H_*NC_*D_*D_];   // [B][H][NC][d][e]
__device__ float g_ks[(size_t)B_*H_*NC_*D_];      // [B][H][NC][D]
__device__ float g_xr[(size_t)M_*HID_];           // tf32-rounded x
__device__ float g_Wt[(size_t)4*HID_*HID_];       // tf32-rounded, transposed W [n][k]
__device__ float g_bias[QROW];                    // concat bq|bk|bv

// ============================ helpers ==================================
__device__ __forceinline__ unsigned f2tf(float x) {
    unsigned u; asm("cvt.rna.tf32.f32 %0, %1;" : "=r"(u) : "f"(x)); return u;
}
__device__ __forceinline__ float f2tff(float x) { return __uint_as_float(f2tf(x)); }
__device__ __forceinline__ void cpasync16(void* s, const void* g) {
    unsigned sa = (unsigned)__cvta_generic_to_shared(s);
    asm volatile("cp.async.cg.shared.global [%0], [%1], 16;\n" :: "r"(sa), "l"(g));
}
#define LDSM_X4(r0, r1, r2, r3, addr) \
    asm volatile("ldmatrix.sync.aligned.m8n8.x4.shared.b16 {%0,%1,%2,%3}, [%4];" \
                 : "=r"(r0), "=r"(r1), "=r"(r2), "=r"(r3) : "r"(addr))
#define MMA_TF32(acc, a, b) \
    asm volatile( \
        "mma.sync.aligned.m16n8k8.row.col.f32.tf32.tf32.f32 " \
        "{%0,%1,%2,%3},{%4,%5,%6,%7},{%8,%9},{%0,%1,%2,%3};\n" \
        : "+f"((acc)[0]), "+f"((acc)[1]), "+f"((acc)[2]), "+f"((acc)[3]) \
        : "r"((a)[0]), "r"((a)[1]), "r"((a)[2]), "r"((a)[3]), \
          "r"((b)[0]), "r"((b)[1]))

// ---------------------------------------------------------------------------
// Elementwise tf32 rounding (RN)
// ---------------------------------------------------------------------------
__global__ __launch_bounds__(256)
void round_tf32_kernel(const float* __restrict__ in, float* __restrict__ out, int n4)
{
    int i = blockIdx.x * 256 + threadIdx.x;
    if (i < n4) {
        float4 v = ((const float4*)in)[i];
        v.x = f2tff(v.x); v.y = f2tff(v.y);
        v.z = f2tff(v.z); v.w = f2tff(v.w);
        ((float4*)out)[i] = v;
    }
}

// ---------------------------------------------------------------------------
// Fused transpose + tf32 round: g_Wt[z][n][k] = round(W_z[k][n])
// ---------------------------------------------------------------------------
__global__ __launch_bounds__(256)
void transpose_round_kernel(const float* __restrict__ W0, const float* __restrict__ W1,
                            const float* __restrict__ W2, const float* __restrict__ W3,
                            float* __restrict__ out)
{
    __shared__ float tile[32][33];
    const int z = blockIdx.z;
    const float* in = (z == 0) ? W0 : (z == 1) ? W1 : (z == 2) ? W2 : W3;
    float* o = out + (size_t)z * HID_ * HID_;

    int x  = blockIdx.x * 32 + threadIdx.x;
    int y0 = blockIdx.y * 32 + threadIdx.y;
    #pragma unroll
    for (int i = 0; i < 4; i++)
        tile[threadIdx.y + i*8][threadIdx.x] =
            f2tff(in[(size_t)(y0 + i*8) * HID_ + x]);
    __syncthreads();
    int x2 = blockIdx.y * 32 + threadIdx.x;
    int y2 = blockIdx.x * 32 + threadIdx.y;
    #pragma unroll
    for (int i = 0; i < 4; i++)
        o[(size_t)(y2 + i*8) * HID_ + x2] = tile[threadIdx.x][threadIdx.y + i*8];
}

// ---------------------------------------------------------------------------
// Concat biases: g_bias = [bq | bk | bv]
// ---------------------------------------------------------------------------
__global__ __launch_bounds__(256)
void bias_concat_kernel(const float* __restrict__ bq, const float* __restrict__ bk,
                        const float* __restrict__ bv)
{
    int i = blockIdx.x * 256 + threadIdx.x;   // 0..6143
    const float* src = (i < HID_) ? bq : (i < 2*HID_) ? bk : bv;
    g_bias[i] = src[i & (HID_-1)];
}

// ===========================================================================
// tf32 mma.sync GEMM (R9 WIN config, unchanged)
// ===========================================================================
#define TSTR 36
#define STG_FLTS (2*128*TSTR)             // 9216 floats per stage
#define G_STAGES 2
#define G_SMEM (G_STAGES*STG_FLTS*4)      // 73728 bytes
#define G_NKT (HID_/32)                   // 64

extern __shared__ unsigned char smem_raw[];

__device__ __forceinline__ void g_load_stage(float* As, float* Bs,
                                             const float* __restrict__ A,
                                             const float* __restrict__ Bt,
                                             int bm, int bn, int kt, int t)
{
    const float* Ag = A + (size_t)(bm*128)*HID_ + kt*32;
    #pragma unroll
    for (int rep = 0; rep < 8; rep++) {
        int q = t + rep*128;              // 0..1023
        int r = q >> 3, c4 = (q & 7) * 4;
        cpasync16(&As[r*TSTR + c4], Ag + (size_t)r*HID_ + c4);
    }
    const float* Bg = Bt + (size_t)(bn*128)*HID_ + kt*32;
    #pragma unroll
    for (int rep = 0; rep < 8; rep++) {
        int q = t + rep*128;
        int r = q >> 3, c4 = (q & 7) * 4;
        cpasync16(&Bs[r*TSTR + c4], Bg + (size_t)r*HID_ + c4);
    }
}

__global__ __launch_bounds__(128)
void gemm_tf32_kernel(const float* __restrict__ A, const float* __restrict__ Bt,
                      const float* __restrict__ bias, float* __restrict__ out,
                      int act_bn, int ostride)
{
    float* sm = (float*)smem_raw;
    const uint32_t smem_base = (uint32_t)__cvta_generic_to_shared(sm);
    const int t = threadIdx.x;
    const int lane = t & 31, warp = t >> 5;
    const int wm = warp >> 1, wn = warp & 1;   // 2x2 warps, 64x64 each
    const int g = lane >> 2, tg = lane & 3;
    const int bn = blockIdx.x, bm = blockIdx.y;
    const bool do_act = bn < act_bn;

    const int a_row = (lane & 15);
    const int a_ch  = (lane >> 4) * 4;
    const int b_row = ((lane >> 4) * 8) + (lane & 7);
    const int b_ch  = ((lane >> 3) & 1) * 4;

    float acc[4][8][4];
    #pragma unroll
    for (int mi = 0; mi < 4; mi++)
        #pragma unroll
        for (int ni = 0; ni < 8; ni++)
            #pragma unroll
            for (int q = 0; q < 4; q++) acc[mi][ni][q] = 0.f;

    #pragma unroll
    for (int st = 0; st < G_STAGES; st++) {
        g_load_stage(sm + st*STG_FLTS, sm + st*STG_FLTS + 128*TSTR,
                     A, Bt, bm, bn, st, t);
        asm volatile("cp.async.commit_group;\n" ::: "memory");
    }

    for (int kt = 0; kt < G_NKT; kt++) {
        const int s = kt & 1;
        if (kt < G_NKT-1) asm volatile("cp.async.wait_group 1;\n" ::: "memory");
        else              asm volatile("cp.async.wait_group 0;\n" ::: "memory");
        __syncthreads();

        const uint32_t Ab = smem_base + (uint32_t)(s*STG_FLTS)*4;
        const uint32_t Bb = Ab + 128*TSTR*4;
        uint32_t a_addr0 = Ab + (uint32_t)(((wm*64 + a_row)*TSTR + a_ch) * 4);
        uint32_t b_addr0 = Bb + (uint32_t)(((wn*64 + b_row)*TSTR + b_ch) * 4);

        #pragma unroll
        for (int kk = 0; kk < 4; kk++) {
            unsigned a[4][4], b[8][2];
            #pragma unroll
            for (int mi = 0; mi < 4; mi++) {
                uint32_t ad = a_addr0 + (uint32_t)(mi*16*TSTR + kk*8) * 4;
                LDSM_X4(a[mi][0], a[mi][1], a[mi][2], a[mi][3], ad);
            }
            #pragma unroll
            for (int p = 0; p < 4; p++) {
                uint32_t bd = b_addr0 + (uint32_t)(p*16*TSTR + kk*8) * 4;
                LDSM_X4(b[2*p][0], b[2*p][1], b[2*p+1][0], b[2*p+1][1], bd);
            }
            #pragma unroll
            for (int mi = 0; mi < 4; mi++)
                #pragma unroll
                for (int ni = 0; ni < 8; ni++)
                    MMA_TF32(acc[mi][ni], a[mi], b[ni]);
        }
        __syncthreads();

        if (kt + G_STAGES < G_NKT) {
            g_load_stage(sm + s*STG_FLTS, sm + s*STG_FLTS + 128*TSTR,
                         A, Bt, bm, bn, kt + G_STAGES, t);
            asm volatile("cp.async.commit_group;\n" ::: "memory");
        }
    }

    // epilogue
    #pragma unroll
    for (int mi = 0; mi < 4; mi++) {
        int row0 = bm*128 + wm*64 + mi*16 + g;
        #pragma unroll
        for (int ni = 0; ni < 8; ni++) {
            int col = bn*128 + wn*64 + ni*8 + 2*tg;
            float b0 = bias[col], b1 = bias[col + 1];
            float v0 = acc[mi][ni][0] + b0;
            float v1 = acc[mi][ni][1] + b1;
            float v2 = acc[mi][ni][2] + b0;
            float v3 = acc[mi][ni][3] + b1;
            if (do_act) {
                v0 = (v0 > 0.f) ? v0 + 1.f : __expf(v0);
                v1 = (v1 > 0.f) ? v1 + 1.f : __expf(v1);
                v2 = (v2 > 0.f) ? v2 + 1.f : __expf(v2);
                v3 = (v3 > 0.f) ? v3 + 1.f : __expf(v3);
            }
            float2 p0; p0.x = v0; p0.y = v1;
            float2 p1; p1.x = v2; p1.y = v3;
            *(float2*)&out[(size_t) row0     *ostride + col] = p0;
            *(float2*)&out[(size_t)(row0 + 8)*ostride + col] = p1;
        }
    }
}

// ===========================================================================
// Chunk KV (tensor-core, R12-proven): kv[d][e] = sum_c kf[c,d]*v[c,e]; ksum[d]
// smem: U1 = vT [e][132], U2 = kfT [d][132]  (135.2 KB)
// ===========================================================================
#define CSTR 132
#define KV_U1 0
#define KV_U2 (128*CSTR)
#define KV_TOT (2*128*CSTR)

__global__ __launch_bounds__(256)
void chunk_kv_mma_kernel()
{
    float* cs = (float*)smem_raw;
    const uint32_t sb = (uint32_t)__cvta_generic_to_shared(cs);
    const int t = threadIdx.x;
    const int lane = t & 31, warp = t >> 5;
    const int wm = warp >> 2, wn = warp & 3;       // 2(d-half) x 4(e-quarter)
    const int g = lane >> 2, tg = lane & 3;
    const int a_row = lane & 15, a_ch = (lane >> 4) * 4;
    const int b_row = ((lane >> 4) * 8) + (lane & 7), b_ch = ((lane >> 3) & 1) * 4;

    const int x = blockIdx.x;
    const int b = x / (H_*NC_);
    const int r = x % (H_*NC_);
    const int h = r / NC_;
    const int n = r % NC_;
    const size_t base_k = ((size_t)(b*S_ + n*C_))*QROW + HID_ + h*D_;

    // transposed, tf32-rounded loads
    #pragma unroll
    for (int rep = 0; rep < 64; rep++) {
        int lin = t + rep*256;
        int c = lin >> 7, d = lin & 127;
        size_t ga = base_k + (size_t)c*QROW + d;
        cs[KV_U2 + d*CSTR + c] = f2tff(g_qkv[ga]);          // kfT[d][c]
        cs[KV_U1 + d*CSTR + c] = f2tff(g_qkv[ga + HID_]);   // vT[e=d][c]
    }
    __syncthreads();

    float acc[4][4][4];
    #pragma unroll
    for (int mi = 0; mi < 4; mi++)
        #pragma unroll
        for (int ni = 0; ni < 4; ni++)
            #pragma unroll
            for (int q = 0; q < 4; q++) acc[mi][ni][q] = 0.f;

    const uint32_t aB = sb + (uint32_t)((KV_U2 + (wm*64 + a_row)*CSTR + a_ch) * 4);
    const uint32_t bB = sb + (uint32_t)((KV_U1 + (wn*32 + b_row)*CSTR + b_ch) * 4);

    #pragma unroll
    for (int kk = 0; kk < 16; kk++) {
        unsigned a[4][4], b[4][2];
        #pragma unroll
        for (int mi = 0; mi < 4; mi++) {
            uint32_t ad = aB + (uint32_t)((mi*16*CSTR + kk*8) * 4);
            LDSM_X4(a[mi][0], a[mi][1], a[mi][2], a[mi][3], ad);
        }
        #pragma unroll
        for (int p = 0; p < 2; p++) {
            uint32_t bd = bB + (uint32_t)((p*16*CSTR + kk*8) * 4);
            LDSM_X4(b[2*p][0], b[2*p][1], b[2*p+1][0], b[2*p+1][1], bd);
        }
        #pragma unroll
        for (int mi = 0; mi < 4; mi++)
            #pragma unroll
            for (int ni = 0; ni < 4; ni++)
                MMA_TF32(acc[mi][ni], a[mi], b[ni]);
    }

    // ksum[d] = rowsum of kfT
    if (t < 128) {
        float s = 0.f;
        const float* row = cs + KV_U2 + t*CSTR;
        #pragma unroll 4
        for (int c = 0; c < 128; c++) s += row[c];
        g_ks[(size_t)x*D_ + t] = s;
    }

    // store kv[d][e]
    const size_t kvb = (size_t)x * (D_*D_);
    #pragma unroll
    for (int mi = 0; mi < 4; mi++) {
        int d0 = wm*64 + mi*16 + g;
        #pragma unroll
        for (int ni = 0; ni < 4; ni++) {
            int e0 = wn*32 + ni*8 + 2*tg;
            float2 p0; p0.x = acc[mi][ni][0]; p0.y = acc[mi][ni][1];
            float2 p1; p1.x = acc[mi][ni][2]; p1.y = acc[mi][ni][3];
            *(float2*)&g_kv[kvb + (size_t) d0     *D_ + e0] = p0;
            *(float2*)&g_kv[kvb + (size_t)(d0 + 8)*D_ + e0] = p1;
        }
    }
}

// ---------------------------------------------------------------------------
// In-place exclusive scans over the chunk axis
// ---------------------------------------------------------------------------
__global__ __launch_bounds__(256)
void scan_kv_kernel()
{
    int f = blockIdx.x * 256 + threadIdx.x;
    int bh = f >> 14;
    int de = f & 16383;
    float* p = g_kv + (size_t)bh * (NC_*D_*D_) + de;
    float run = 0.f;
    #pragma unroll
    for (int n = 0; n < NC_; n++) {
        float tv = p[(size_t)n * (D_*D_)];
        p[(size_t)n * (D_*D_)] = run;
        run += tv;
    }
}

__global__ __launch_bounds__(256)
void scan_ks_kernel()
{
    int f = blockIdx.x * 256 + threadIdx.x;
    int bh = f >> 7;
    int d  = f & 127;
    float* p = g_ks + (size_t)bh * (NC_*D_) + d;
    float run = 0.f;
    #pragma unroll
    for (int n = 0; n < NC_; n++) {
        float tv = p[n*D_];
        p[n*D_] = run;
        run += tv;
    }
}

// ===========================================================================
// Per-chunk attention (fp32 SIMT, HALF-CHUNK tiles): 64 c-rows per CTA,
// smem 108.1 KB -> 2 CTAs/SM (16 warps). Same instruction mix and per-output
// accumulation order as the R12-proven kernel; only the tiling changes.
// ===========================================================================
#define HS_Q   0                       // 64 x 129
#define HS_B   (64*129)                // 128 x 129 (kf; rows 0..63 reused for A)
#define HS_T   (HS_B + 128*129)        // 16 x 129
#define HS_KS  (HS_T + 16*129)         // 128
#define HS_Z   (HS_KS + 128)           // 64
#define HS_TOT (HS_Z + 64)             // 27024 floats = 108096 B

__global__ __launch_bounds__(256)
void chunk_attn_half_kernel()
{
    float* cs = (float*)smem_raw;
    float* s_q  = cs + HS_Q;
    float* s_B  = cs + HS_B;
    float* s_t  = cs + HS_T;
    float* s_ks = cs + HS_KS;
    float* s_z  = cs + HS_Z;

    const int t = threadIdx.x;
    const int lane = t & 31, warp = t >> 5;
    const int tcw = lane >> 3, tkw = lane & 7;
    const int wc  = warp >> 1, wk  = warp & 1;
    const int c0 = (wc*4 + tcw) * 4;     // local row group (4 rows) in 0..63
    const int k0 = (wk*8 + tkw) * 8;     // col group (8 cols) in 0..127

    const int xh = blockIdx.x;           // chunk*2 + half
    const int x = xh >> 1;
    const int half = xh & 1;
    const int b = x / (H_*NC_);
    const int r = x % (H_*NC_);
    const int h = r / NC_;
    const int n = r % NC_;
    const int crow0 = half * 64;

    const size_t base  = ((size_t)(b*S_ + n*C_))*QROW + h*D_;   // q in g_qkv
    const size_t obase = ((size_t)(b*S_ + n*C_))*HID_ + h*D_;   // g_attn
    const size_t kvb   = (size_t)x * (D_*D_);

    // loads: s_q = qf local 64 rows; s_B = kf full 128 rows
    #pragma unroll
    for (int rep = 0; rep < 32; rep++) {
        int lin = t + rep*256;
        int row = lin >> 7, d = lin & 127;
        s_q[row*129 + d] = g_qkv[base + (size_t)(crow0 + row)*QROW + d];
    }
    #pragma unroll
    for (int rep = 0; rep < 64; rep++) {
        int lin = t + rep*256;
        int row = lin >> 7, d = lin & 127;
        s_B[row*129 + d] = g_qkv[base + (size_t)row*QROW + HID_ + d];
    }
    if (t < 128) s_ks[t] = g_ks[(size_t)x*D_ + t];
    __syncthreads();

    float acc[4][8];
    #pragma unroll
    for (int i = 0; i < 4; i++)
        #pragma unroll
        for (int j = 0; j < 8; j++) acc[i][j] = 0.f;

    // phase1: A(local 64 x 128) = qf_local @ kf^T
    #pragma unroll 2
    for (int dd = 0; dd < 128; dd++) {
        float a[4], bb[8];
        #pragma unroll
        for (int i = 0; i < 4; i++) a[i]  = s_q[(c0 + i)*129 + dd];
        #pragma unroll
        for (int j = 0; j < 8; j++) bb[j] = s_B[(k0 + j)*129 + dd];
        #pragma unroll
        for (int i = 0; i < 4; i++)
            #pragma unroll
            for (int j = 0; j < 8; j++)
                acc[i][j] = fmaf(a[i], bb[j], acc[i][j]);
    }
    __syncthreads();   // kf fully consumed

    // write masked A into s_B rows 0..63 (overwriting kf's first half)
    #pragma unroll
    for (int i = 0; i < 4; i++)
        #pragma unroll
        for (int j = 0; j < 8; j++) {
            float v = ((k0 + j) <= (crow0 + c0 + i)) ? acc[i][j] : 0.f;
            s_B[(c0 + i)*129 + k0 + j] = v;
            acc[i][j] = 0.f;
        }
    __syncthreads();

    // z normalizers (local rows)
    if (t < 64) {
        float z = EPS_;
        const float* arow = s_B + t*129;
        #pragma unroll 4
        for (int k = 0; k < 128; k++) z += arow[k];
        const float* qrow = s_q + t*129;
        #pragma unroll 4
        for (int d2 = 0; d2 < 128; d2++) z += qrow[d2] * s_ks[d2];
        s_z[t] = z;
    }

    // phase4: acc = A@v + qf@kv_ex (256-deep reduction, tiles of 16)
    for (int rt = 0; rt < 16; rt++) {
        #pragma unroll
        for (int rep = 0; rep < 8; rep++) {
            int lin = t + rep*256;
            int row = lin >> 7, e = lin & 127;
            float v;
            if (rt < 8)
                v = g_qkv[base + (size_t)(rt*16 + row)*QROW + 2*HID_ + e];
            else
                v = g_kv[kvb + (size_t)((rt - 8)*16 + row)*D_ + e];
            s_t[row*129 + e] = v;
        }
        __syncthreads();

        const float* op1 = (rt < 8) ? s_B : s_q;
        const int colb = (rt*16) & 127;
        #pragma unroll 4
        for (int rr = 0; rr < 16; rr++) {
            int col = colb + rr;
            float a[4], bb[8];
            #pragma unroll
            for (int i = 0; i < 4; i++) a[i]  = op1[(c0 + i)*129 + col];
            #pragma unroll
            for (int j = 0; j < 8; j++) bb[j] = s_t[rr*129 + k0 + j];
            #pragma unroll
            for (int i = 0; i < 4; i++)
                #pragma unroll
                for (int j = 0; j < 8; j++)
                    acc[i][j] = fmaf(a[i], bb[j], acc[i][j]);
        }
        __syncthreads();
    }

    // normalize + tf32-round store
    #pragma unroll
    for (int i = 0; i < 4; i++) {
        float inv = 1.f / s_z[c0 + i];
        #pragma unroll
        for (int j = 0; j < 8; j++)
            g_attn[obase + (size_t)(crow0 + c0 + i)*HID_ + k0 + j] =
                __uint_as_float(f2tf(acc[i][j] * inv));
    }
}

// ---------------------------------------------------------------------------
extern "C" void kernel_launch(void* const* d_in, const int* in_sizes, int n_in,
                              void* d_out, int out_size)
{
    const float* x  = (const float*)d_in[0];
    const float* Wq = (const float*)d_in[1];
    const float* bq = (const float*)d_in[2];
    const float* Wk = (const float*)d_in[3];
    const float* bk = (const float*)d_in[4];
    const float* Wv = (const float*)d_in[5];
    const float* bv = (const float*)d_in[6];
    const float* Wo = (const float*)d_in[7];
    const float* bo = (const float*)d_in[8];

    float *p_qkv, *p_attn, *p_xr, *p_Wt, *p_bias;
    cudaGetSymbolAddress((void**)&p_qkv,  g_qkv);
    cudaGetSymbolAddress((void**)&p_attn, g_attn);
    cudaGetSymbolAddress((void**)&p_xr,   g_xr);
    cudaGetSymbolAddress((void**)&p_Wt,   g_Wt);
    cudaGetSymbolAddress((void**)&p_bias, g_bias);

    cudaFuncSetAttribute(gemm_tf32_kernel,
                         cudaFuncAttributeMaxDynamicSharedMemorySize, G_SMEM);
    cudaFuncSetAttribute(chunk_kv_mma_kernel,
                         cudaFuncAttributeMaxDynamicSharedMemorySize, KV_TOT*4);
    cudaFuncSetAttribute(chunk_attn_half_kernel,
                         cudaFuncAttributeMaxDynamicSharedMemorySize, HS_TOT*4);

    const size_t WSZ = (size_t)HID_ * HID_;

    // pre-round x; fused transpose+round weights; concat biases
    int xn4 = (int)((size_t)M_*HID_/4);
    round_tf32_kernel<<<(xn4+255)/256, 256>>>(x, p_xr, xn4);
    dim3 tb(32, 8), tg(HID_/32, HID_/32, 4);
    transpose_round_kernel<<<tg, tb>>>(Wq, Wk, Wv, Wo, p_Wt);
    bias_concat_kernel<<<QROW/256, 256>>>(bq, bk, bv);

    // fused QKV projection: N=6144, one launch (48 x 64 grid)
    dim3 gg_qkv(3*HID_/128, M_/128);
    gemm_tf32_kernel<<<gg_qkv, 128, G_SMEM>>>(p_xr, p_Wt, p_bias, p_qkv,
                                              /*act_bn=*/32, /*ostride=*/QROW);

    chunk_kv_mma_kernel<<<B_*H_*NC_, 256, KV_TOT*4>>>();
    scan_kv_kernel<<<(B_*H_*D_*D_)/256, 256>>>();
    scan_ks_kernel<<<(B_*H_*D_)/256, 256>>>();
    chunk_attn_half_kernel<<<B_*H_*NC_*2, 256, HS_TOT*4>>>();

    // output projection
    dim3 gg_o(HID_/128, M_/128);
    gemm_tf32_kernel<<<gg_o, 128, G_SMEM>>>(p_attn, p_Wt + 3*WSZ, bo, (float*)d_out,
                                            /*act_bn=*/0, /*ostride=*/HID_);
}

// round 17
// speedup vs baseline: 1.0313x; 1.0313x over previous
#include <cuda_runtime.h>
#include <cstdint>

// Problem constants
#define B_   2
#define S_   4096
#define H_   16
#define D_   128
#define HID_ 2048
#define C_   128
#define NC_  32
#define M_   (B_*S_)   // 8192 rows
#define EPS_ 1e-6f
#define QROW (3*HID_)  // 6144: fused q|k|v row stride

// ---------------- scratch (device globals; no allocs allowed) ----------------
__device__ float g_qkv[(size_t)M_*QROW];          // [M][q|k|v]
__device__ float g_attn[(size_t)M_*HID_];
__device__ float g_kv[(size_t)B_*H_*NC_*D_*D_];   // [B][H][NC][d][e]
__device__ float g_ks[(size_t)B_*H_*NC_*D_];      // [B][H][NC][D]
__device__ float g_xr[(size_t)M_*HID_];           // tf32-rounded x
__device__ float g_Wt[(size_t)4*HID_*HID_];       // tf32-rounded, transposed W [n][k]
__device__ float g_bias[QROW];                    // concat bq|bk|bv

// ============================ helpers ==================================
__device__ __forceinline__ unsigned f2tf(float x) {
    unsigned u; asm("cvt.rna.tf32.f32 %0, %1;" : "=r"(u) : "f"(x)); return u;
}
__device__ __forceinline__ float f2tff(float x) { return __uint_as_float(f2tf(x)); }
__device__ __forceinline__ void cpasync16(void* s, const void* g) {
    unsigned sa = (unsigned)__cvta_generic_to_shared(s);
    asm volatile("cp.async.cg.shared.global [%0], [%1], 16;\n" :: "r"(sa), "l"(g));
}
#define LDSM_X4(r0, r1, r2, r3, addr) \
    asm volatile("ldmatrix.sync.aligned.m8n8.x4.shared.b16 {%0,%1,%2,%3}, [%4];" \
                 : "=r"(r0), "=r"(r1), "=r"(r2), "=r"(r3) : "r"(addr))
#define MMA_TF32(acc, a, b) \
    asm volatile( \
        "mma.sync.aligned.m16n8k8.row.col.f32.tf32.tf32.f32 " \
        "{%0,%1,%2,%3},{%4,%5,%6,%7},{%8,%9},{%0,%1,%2,%3};\n" \
        : "+f"((acc)[0]), "+f"((acc)[1]), "+f"((acc)[2]), "+f"((acc)[3]) \
        : "r"((a)[0]), "r"((a)[1]), "r"((a)[2]), "r"((a)[3]), \
          "r"((b)[0]), "r"((b)[1]))

// ---------------------------------------------------------------------------
// Elementwise tf32 rounding (RN)
// ---------------------------------------------------------------------------
__global__ __launch_bounds__(256)
void round_tf32_kernel(const float* __restrict__ in, float* __restrict__ out, int n4)
{
    int i = blockIdx.x * 256 + threadIdx.x;
    if (i < n4) {
        float4 v = ((const float4*)in)[i];
        v.x = f2tff(v.x); v.y = f2tff(v.y);
        v.z = f2tff(v.z); v.w = f2tff(v.w);
        ((float4*)out)[i] = v;
    }
}

// ---------------------------------------------------------------------------
// Fused transpose + tf32 round: g_Wt[z][n][k] = round(W_z[k][n])
// ---------------------------------------------------------------------------
__global__ __launch_bounds__(256)
void transpose_round_kernel(const float* __restrict__ W0, const float* __restrict__ W1,
                            const float* __restrict__ W2, const float* __restrict__ W3,
                            float* __restrict__ out)
{
    __shared__ float tile[32][33];
    const int z = blockIdx.z;
    const float* in = (z == 0) ? W0 : (z == 1) ? W1 : (z == 2) ? W2 : W3;
    float* o = out + (size_t)z * HID_ * HID_;

    int x  = blockIdx.x * 32 + threadIdx.x;
    int y0 = blockIdx.y * 32 + threadIdx.y;
    #pragma unroll
    for (int i = 0; i < 4; i++)
        tile[threadIdx.y + i*8][threadIdx.x] =
            f2tff(in[(size_t)(y0 + i*8) * HID_ + x]);
    __syncthreads();
    int x2 = blockIdx.y * 32 + threadIdx.x;
    int y2 = blockIdx.x * 32 + threadIdx.y;
    #pragma unroll
    for (int i = 0; i < 4; i++)
        o[(size_t)(y2 + i*8) * HID_ + x2] = tile[threadIdx.x][threadIdx.y + i*8];
}

// ---------------------------------------------------------------------------
// Concat biases: g_bias = [bq | bk | bv]
// ---------------------------------------------------------------------------
__global__ __launch_bounds__(256)
void bias_concat_kernel(const float* __restrict__ bq, const float* __restrict__ bk,
                        const float* __restrict__ bv)
{
    int i = blockIdx.x * 256 + threadIdx.x;   // 0..6143
    const float* src = (i < HID_) ? bq : (i < 2*HID_) ? bk : bv;
    g_bias[i] = src[i & (HID_-1)];
}

// ===========================================================================
// tf32 mma.sync GEMM (R9 WIN config, unchanged)
// ===========================================================================
#define TSTR 36
#define STG_FLTS (2*128*TSTR)             // 9216 floats per stage
#define G_STAGES 2
#define G_SMEM (G_STAGES*STG_FLTS*4)      // 73728 bytes
#define G_NKT (HID_/32)                   // 64

extern __shared__ unsigned char smem_raw[];

__device__ __forceinline__ void g_load_stage(float* As, float* Bs,
                                             const float* __restrict__ A,
                                             const float* __restrict__ Bt,
                                             int bm, int bn, int kt, int t)
{
    const float* Ag = A + (size_t)(bm*128)*HID_ + kt*32;
    #pragma unroll
    for (int rep = 0; rep < 8; rep++) {
        int q = t + rep*128;              // 0..1023
        int r = q >> 3, c4 = (q & 7) * 4;
        cpasync16(&As[r*TSTR + c4], Ag + (size_t)r*HID_ + c4);
    }
    const float* Bg = Bt + (size_t)(bn*128)*HID_ + kt*32;
    #pragma unroll
    for (int rep = 0; rep < 8; rep++) {
        int q = t + rep*128;
        int r = q >> 3, c4 = (q & 7) * 4;
        cpasync16(&Bs[r*TSTR + c4], Bg + (size_t)r*HID_ + c4);
    }
}

__global__ __launch_bounds__(128)
void gemm_tf32_kernel(const float* __restrict__ A, const float* __restrict__ Bt,
                      const float* __restrict__ bias, float* __restrict__ out,
                      int act_bn, int ostride)
{
    float* sm = (float*)smem_raw;
    const uint32_t smem_base = (uint32_t)__cvta_generic_to_shared(sm);
    const int t = threadIdx.x;
    const int lane = t & 31, warp = t >> 5;
    const int wm = warp >> 1, wn = warp & 1;   // 2x2 warps, 64x64 each
    const int g = lane >> 2, tg = lane & 3;
    const int bn = blockIdx.x, bm = blockIdx.y;
    const bool do_act = bn < act_bn;

    const int a_row = (lane & 15);
    const int a_ch  = (lane >> 4) * 4;
    const int b_row = ((lane >> 4) * 8) + (lane & 7);
    const int b_ch  = ((lane >> 3) & 1) * 4;

    float acc[4][8][4];
    #pragma unroll
    for (int mi = 0; mi < 4; mi++)
        #pragma unroll
        for (int ni = 0; ni < 8; ni++)
            #pragma unroll
            for (int q = 0; q < 4; q++) acc[mi][ni][q] = 0.f;

    #pragma unroll
    for (int st = 0; st < G_STAGES; st++) {
        g_load_stage(sm + st*STG_FLTS, sm + st*STG_FLTS + 128*TSTR,
                     A, Bt, bm, bn, st, t);
        asm volatile("cp.async.commit_group;\n" ::: "memory");
    }

    for (int kt = 0; kt < G_NKT; kt++) {
        const int s = kt & 1;
        if (kt < G_NKT-1) asm volatile("cp.async.wait_group 1;\n" ::: "memory");
        else              asm volatile("cp.async.wait_group 0;\n" ::: "memory");
        __syncthreads();

        const uint32_t Ab = smem_base + (uint32_t)(s*STG_FLTS)*4;
        const uint32_t Bb = Ab + 128*TSTR*4;
        uint32_t a_addr0 = Ab + (uint32_t)(((wm*64 + a_row)*TSTR + a_ch) * 4);
        uint32_t b_addr0 = Bb + (uint32_t)(((wn*64 + b_row)*TSTR + b_ch) * 4);

        #pragma unroll
        for (int kk = 0; kk < 4; kk++) {
            unsigned a[4][4], b[8][2];
            #pragma unroll
            for (int mi = 0; mi < 4; mi++) {
                uint32_t ad = a_addr0 + (uint32_t)(mi*16*TSTR + kk*8) * 4;
                LDSM_X4(a[mi][0], a[mi][1], a[mi][2], a[mi][3], ad);
            }
            #pragma unroll
            for (int p = 0; p < 4; p++) {
                uint32_t bd = b_addr0 + (uint32_t)(p*16*TSTR + kk*8) * 4;
                LDSM_X4(b[2*p][0], b[2*p][1], b[2*p+1][0], b[2*p+1][1], bd);
            }
            #pragma unroll
            for (int mi = 0; mi < 4; mi++)
                #pragma unroll
                for (int ni = 0; ni < 8; ni++)
                    MMA_TF32(acc[mi][ni], a[mi], b[ni]);
        }
        __syncthreads();

        if (kt + G_STAGES < G_NKT) {
            g_load_stage(sm + s*STG_FLTS, sm + s*STG_FLTS + 128*TSTR,
                         A, Bt, bm, bn, kt + G_STAGES, t);
            asm volatile("cp.async.commit_group;\n" ::: "memory");
        }
    }

    // epilogue
    #pragma unroll
    for (int mi = 0; mi < 4; mi++) {
        int row0 = bm*128 + wm*64 + mi*16 + g;
        #pragma unroll
        for (int ni = 0; ni < 8; ni++) {
            int col = bn*128 + wn*64 + ni*8 + 2*tg;
            float b0 = bias[col], b1 = bias[col + 1];
            float v0 = acc[mi][ni][0] + b0;
            float v1 = acc[mi][ni][1] + b1;
            float v2 = acc[mi][ni][2] + b0;
            float v3 = acc[mi][ni][3] + b1;
            if (do_act) {
                v0 = (v0 > 0.f) ? v0 + 1.f : __expf(v0);
                v1 = (v1 > 0.f) ? v1 + 1.f : __expf(v1);
                v2 = (v2 > 0.f) ? v2 + 1.f : __expf(v2);
                v3 = (v3 > 0.f) ? v3 + 1.f : __expf(v3);
            }
            float2 p0; p0.x = v0; p0.y = v1;
            float2 p1; p1.x = v2; p1.y = v3;
            *(float2*)&out[(size_t) row0     *ostride + col] = p0;
            *(float2*)&out[(size_t)(row0 + 8)*ostride + col] = p1;
        }
    }
}

// ===========================================================================
// Chunk KV (tensor-core, R12-proven): kv[d][e] = sum_c kf[c,d]*v[c,e]; ksum[d]
// smem: U1 = vT [e][132], U2 = kfT [d][132]  (135.2 KB)
// ===========================================================================
#define CSTR 132
#define KV_U1 0
#define KV_U2 (128*CSTR)
#define KV_TOT (2*128*CSTR)

__global__ __launch_bounds__(256)
void chunk_kv_mma_kernel()
{
    float* cs = (float*)smem_raw;
    const uint32_t sb = (uint32_t)__cvta_generic_to_shared(cs);
    const int t = threadIdx.x;
    const int lane = t & 31, warp = t >> 5;
    const int wm = warp >> 2, wn = warp & 3;       // 2(d-half) x 4(e-quarter)
    const int g = lane >> 2, tg = lane & 3;
    const int a_row = lane & 15, a_ch = (lane >> 4) * 4;
    const int b_row = ((lane >> 4) * 8) + (lane & 7), b_ch = ((lane >> 3) & 1) * 4;

    const int x = blockIdx.x;
    const int b = x / (H_*NC_);
    const int r = x % (H_*NC_);
    const int h = r / NC_;
    const int n = r % NC_;
    const size_t base_k = ((size_t)(b*S_ + n*C_))*QROW + HID_ + h*D_;

    // transposed, tf32-rounded loads
    #pragma unroll
    for (int rep = 0; rep < 64; rep++) {
        int lin = t + rep*256;
        int c = lin >> 7, d = lin & 127;
        size_t ga = base_k + (size_t)c*QROW + d;
        cs[KV_U2 + d*CSTR + c] = f2tff(g_qkv[ga]);          // kfT[d][c]
        cs[KV_U1 + d*CSTR + c] = f2tff(g_qkv[ga + HID_]);   // vT[e=d][c]
    }
    __syncthreads();

    float acc[4][4][4];
    #pragma unroll
    for (int mi = 0; mi < 4; mi++)
        #pragma unroll
        for (int ni = 0; ni < 4; ni++)
            #pragma unroll
            for (int q = 0; q < 4; q++) acc[mi][ni][q] = 0.f;

    const uint32_t aB = sb + (uint32_t)((KV_U2 + (wm*64 + a_row)*CSTR + a_ch) * 4);
    const uint32_t bB = sb + (uint32_t)((KV_U1 + (wn*32 + b_row)*CSTR + b_ch) * 4);

    #pragma unroll
    for (int kk = 0; kk < 16; kk++) {
        unsigned a[4][4], b[4][2];
        #pragma unroll
        for (int mi = 0; mi < 4; mi++) {
            uint32_t ad = aB + (uint32_t)((mi*16*CSTR + kk*8) * 4);
            LDSM_X4(a[mi][0], a[mi][1], a[mi][2], a[mi][3], ad);
        }
        #pragma unroll
        for (int p = 0; p < 2; p++) {
            uint32_t bd = bB + (uint32_t)((p*16*CSTR + kk*8) * 4);
            LDSM_X4(b[2*p][0], b[2*p][1], b[2*p+1][0], b[2*p+1][1], bd);
        }
        #pragma unroll
        for (int mi = 0; mi < 4; mi++)
            #pragma unroll
            for (int ni = 0; ni < 4; ni++)
                MMA_TF32(acc[mi][ni], a[mi], b[ni]);
    }

    // ksum[d] = rowsum of kfT
    if (t < 128) {
        float s = 0.f;
        const float* row = cs + KV_U2 + t*CSTR;
        #pragma unroll 4
        for (int c = 0; c < 128; c++) s += row[c];
        g_ks[(size_t)x*D_ + t] = s;
    }

    // store kv[d][e]
    const size_t kvb = (size_t)x * (D_*D_);
    #pragma unroll
    for (int mi = 0; mi < 4; mi++) {
        int d0 = wm*64 + mi*16 + g;
        #pragma unroll
        for (int ni = 0; ni < 4; ni++) {
            int e0 = wn*32 + ni*8 + 2*tg;
            float2 p0; p0.x = acc[mi][ni][0]; p0.y = acc[mi][ni][1];
            float2 p1; p1.x = acc[mi][ni][2]; p1.y = acc[mi][ni][3];
            *(float2*)&g_kv[kvb + (size_t) d0     *D_ + e0] = p0;
            *(float2*)&g_kv[kvb + (size_t)(d0 + 8)*D_ + e0] = p1;
        }
    }
}

// ---------------------------------------------------------------------------
// In-place exclusive scans over the chunk axis
// ---------------------------------------------------------------------------
__global__ __launch_bounds__(256)
void scan_kv_kernel()
{
    int f = blockIdx.x * 256 + threadIdx.x;
    int bh = f >> 14;
    int de = f & 16383;
    float* p = g_kv + (size_t)bh * (NC_*D_*D_) + de;
    float run = 0.f;
    #pragma unroll
    for (int n = 0; n < NC_; n++) {
        float tv = p[(size_t)n * (D_*D_)];
        p[(size_t)n * (D_*D_)] = run;
        run += tv;
    }
}

__global__ __launch_bounds__(256)
void scan_ks_kernel()
{
    int f = blockIdx.x * 256 + threadIdx.x;
    int bh = f >> 7;
    int d  = f & 127;
    float* p = g_ks + (size_t)bh * (NC_*D_) + d;
    float run = 0.f;
    #pragma unroll
    for (int n = 0; n < NC_; n++) {
        float tv = p[n*D_];
        p[n*D_] = run;
        run += tv;
    }
}

// ---------------------------------------------------------------------------
// Per-chunk attention (fp32 SIMT, full-chunk R12 structure).
// Micro-opt: s_t stride 132 (16B-aligned rows) -> phase-4 B loads via LDS.128;
// tile fills via LDG.128. FMA order per output unchanged (bit-identical math).
// ---------------------------------------------------------------------------
#define TSTR2 132
#define CS_Q   0
#define CS_B   (128*129)
#define CS_T   (2*128*129)
#define CS_KS  (CS_T + 16*TSTR2)
#define CS_Z   (CS_KS + 128)
#define CS_TOT (CS_Z + 128)     // 35392 floats = 141568 B

__global__ __launch_bounds__(256)
void chunk_attn_kernel()
{
    float* cs = (float*)smem_raw;
    float* s_q  = cs + CS_Q;
    float* s_B  = cs + CS_B;
    float* s_t  = cs + CS_T;
    float* s_ks = cs + CS_KS;
    float* s_z  = cs + CS_Z;

    const int t = threadIdx.x;
    const int lane = t & 31, warp = t >> 5;
    const int tcw = lane >> 3, tkw = lane & 7;
    const int wc  = warp >> 1, wk  = warp & 1;
    const int c0 = (wc*4 + tcw) * 8;
    const int k0 = (wk*8 + tkw) * 8;

    const int x = blockIdx.x;
    const int b = x / (H_*NC_);
    const int r = x % (H_*NC_);
    const int h = r / NC_;
    const int n = r % NC_;

    const size_t base  = ((size_t)(b*S_ + n*C_))*QROW + h*D_;   // q in g_qkv
    const size_t obase = ((size_t)(b*S_ + n*C_))*HID_ + h*D_;   // g_attn
    const size_t kvb   = (size_t)x * (D_*D_);

    // fills via LDG.128 (scatter STS; stride-129 rows can't take vector stores)
    #pragma unroll
    for (int rep = 0; rep < 16; rep++) {
        int lin = t + rep*256;          // 0..4095 float4 units
        int row = lin >> 5, c4 = (lin & 31) * 4;
        size_t ga = base + (size_t)row*QROW + c4;
        float4 q4 = *(const float4*)&g_qkv[ga];
        float4 k4 = *(const float4*)&g_qkv[ga + HID_];
        float* qd = s_q + row*129 + c4;
        float* kd = s_B + row*129 + c4;
        qd[0] = q4.x; qd[1] = q4.y; qd[2] = q4.z; qd[3] = q4.w;
        kd[0] = k4.x; kd[1] = k4.y; kd[2] = k4.z; kd[3] = k4.w;
    }
    if (t < 128) s_ks[t] = g_ks[(size_t)x*D_ + t];
    __syncthreads();

    float acc[8][8];
    #pragma unroll
    for (int i = 0; i < 8; i++)
        #pragma unroll
        for (int j = 0; j < 8; j++) acc[i][j] = 0.f;

    #pragma unroll 2
    for (int dd = 0; dd < 128; dd++) {
        float a[8], bb[8];
        #pragma unroll
        for (int i = 0; i < 8; i++) a[i]  = s_q[(c0 + i)*129 + dd];
        #pragma unroll
        for (int j = 0; j < 8; j++) bb[j] = s_B[(k0 + j)*129 + dd];
        #pragma unroll
        for (int i = 0; i < 8; i++)
            #pragma unroll
            for (int j = 0; j < 8; j++)
                acc[i][j] = fmaf(a[i], bb[j], acc[i][j]);
    }
    __syncthreads();

    #pragma unroll
    for (int i = 0; i < 8; i++)
        #pragma unroll
        for (int j = 0; j < 8; j++) {
            float v = ((k0 + j) <= (c0 + i)) ? acc[i][j] : 0.f;
            s_B[(c0 + i)*129 + k0 + j] = v;
            acc[i][j] = 0.f;
        }
    __syncthreads();

    if (t < 128) {
        float z = EPS_;
        const float* arow = s_B + t*129;
        #pragma unroll 4
        for (int k = 0; k < 128; k++) z += arow[k];
        const float* qrow = s_q + t*129;
        #pragma unroll 4
        for (int d2 = 0; d2 < 128; d2++) z += qrow[d2] * s_ks[d2];
        s_z[t] = z;
    }

    for (int rt = 0; rt < 16; rt++) {
        // tile fill: 16x128 floats = 512 float4, 2 reps, LDG.128 + STS.128
        #pragma unroll
        for (int rep = 0; rep < 2; rep++) {
            int lin = t + rep*256;          // 0..511
            int row = lin >> 5, c4 = (lin & 31) * 4;
            float4 v4;
            if (rt < 8)
                v4 = *(const float4*)&g_qkv[base + (size_t)(rt*16 + row)*QROW
                                            + 2*HID_ + c4];
            else
                v4 = *(const float4*)&g_kv[kvb + (size_t)((rt - 8)*16 + row)*D_ + c4];
            *(float4*)&s_t[row*TSTR2 + c4] = v4;
        }
        __syncthreads();

        const float* op1 = (rt < 8) ? s_B : s_q;
        const int colb = (rt*16) & 127;
        #pragma unroll 4
        for (int rr = 0; rr < 16; rr++) {
            int col = colb + rr;
            float a[8], bb[8];
            #pragma unroll
            for (int i = 0; i < 8; i++) a[i]  = op1[(c0 + i)*129 + col];
            float4 b0 = *(const float4*)&s_t[rr*TSTR2 + k0];
            float4 b1 = *(const float4*)&s_t[rr*TSTR2 + k0 + 4];
            bb[0] = b0.x; bb[1] = b0.y; bb[2] = b0.z; bb[3] = b0.w;
            bb[4] = b1.x; bb[5] = b1.y; bb[6] = b1.z; bb[7] = b1.w;
            #pragma unroll
            for (int i = 0; i < 8; i++)
                #pragma unroll
                for (int j = 0; j < 8; j++)
                    acc[i][j] = fmaf(a[i], bb[j], acc[i][j]);
        }
        __syncthreads();
    }

    float zz[8];
    #pragma unroll
    for (int i = 0; i < 8; i++) zz[i] = s_z[c0 + i];
    #pragma unroll
    for (int i = 0; i < 8; i++) {
        float inv = 1.f / zz[i];
        #pragma unroll
        for (int j = 0; j < 8; j++)
            g_attn[obase + (size_t)(c0 + i)*HID_ + k0 + j] =
                __uint_as_float(f2tf(acc[i][j] * inv));
    }
}

// ---------------------------------------------------------------------------
extern "C" void kernel_launch(void* const* d_in, const int* in_sizes, int n_in,
                              void* d_out, int out_size)
{
    const float* x  = (const float*)d_in[0];
    const float* Wq = (const float*)d_in[1];
    const float* bq = (const float*)d_in[2];
    const float* Wk = (const float*)d_in[3];
    const float* bk = (const float*)d_in[4];
    const float* Wv = (const float*)d_in[5];
    const float* bv = (const float*)d_in[6];
    const float* Wo = (const float*)d_in[7];
    const float* bo = (const float*)d_in[8];

    float *p_qkv, *p_attn, *p_xr, *p_Wt, *p_bias;
    cudaGetSymbolAddress((void**)&p_qkv,  g_qkv);
    cudaGetSymbolAddress((void**)&p_attn, g_attn);
    cudaGetSymbolAddress((void**)&p_xr,   g_xr);
    cudaGetSymbolAddress((void**)&p_Wt,   g_Wt);
    cudaGetSymbolAddress((void**)&p_bias, g_bias);

    const size_t csmem = (size_t)CS_TOT * sizeof(float);
    cudaFuncSetAttribute(gemm_tf32_kernel,
                         cudaFuncAttributeMaxDynamicSharedMemorySize, G_SMEM);
    cudaFuncSetAttribute(chunk_attn_kernel,
                         cudaFuncAttributeMaxDynamicSharedMemorySize, (int)csmem);
    cudaFuncSetAttribute(chunk_kv_mma_kernel,
                         cudaFuncAttributeMaxDynamicSharedMemorySize, KV_TOT*4);

    const size_t WSZ = (size_t)HID_ * HID_;

    // pre-round x; fused transpose+round weights; concat biases
    int xn4 = (int)((size_t)M_*HID_/4);
    round_tf32_kernel<<<(xn4+255)/256, 256>>>(x, p_xr, xn4);
    dim3 tb(32, 8), tg(HID_/32, HID_/32, 4);
    transpose_round_kernel<<<tg, tb>>>(Wq, Wk, Wv, Wo, p_Wt);
    bias_concat_kernel<<<QROW/256, 256>>>(bq, bk, bv);

    // fused QKV projection: N=6144, one launch (48 x 64 grid)
    dim3 gg_qkv(3*HID_/128, M_/128);
    gemm_tf32_kernel<<<gg_qkv, 128, G_SMEM>>>(p_xr, p_Wt, p_bias, p_qkv,
                                              /*act_bn=*/32, /*ostride=*/QROW);

    chunk_kv_mma_kernel<<<B_*H_*NC_, 256, KV_TOT*4>>>();
    scan_kv_kernel<<<(B_*H_*D_*D_)/256, 256>>>();
    scan_ks_kernel<<<(B_*H_*D_)/256, 256>>>();
    chunk_attn_kernel<<<B_*H_*NC_, 256, csmem>>>();

    // output projection
    dim3 gg_o(HID_/128, M_/128);
    gemm_tf32_kernel<<<gg_o, 128, G_SMEM>>>(p_attn, p_Wt + 3*WSZ, bo, (float*)d_out,
                                            /*act_bn=*/0, /*ostride=*/HID_);
}